// round 12
// baseline (speedup 1.0000x reference)
#include <cuda_runtime.h>
#include <cuda_fp16.h>
#include <cstdint>

// Fused edge-MLP graph network. Edge: fp16 single-pass (R11, best). Node: fp16
// hi/lo 3-pass tensor cores. v12.
#define N_MAX 16384
#define SC    128
#define RED   32
#define PWN   32
#define PAIR  128
#define XDIM  96

#define TPB  256
#define ETPB 512
#define TS   128
#define PX   136     // fp16 element pitch of activation/weight planes

__device__ float g_t[(size_t)N_MAX * RED];
__device__ float g_tmp[(size_t)N_MAX * PAIR];

// ---------------------------------------------------------------------------
// helpers
// ---------------------------------------------------------------------------
__device__ __forceinline__ uint32_t smem_addr32(const void* p) {
    uint32_t a;
    asm("{ .reg .u64 t; cvta.to.shared.u64 t, %1; cvt.u32.u64 %0, t; }" : "=r"(a) : "l"(p));
    return a;
}
__device__ __forceinline__ void ldsm4(uint32_t& r0, uint32_t& r1, uint32_t& r2,
                                      uint32_t& r3, uint32_t addr) {
    asm volatile("ldmatrix.sync.aligned.m8n8.x4.shared.b16 {%0,%1,%2,%3}, [%4];"
                 : "=r"(r0), "=r"(r1), "=r"(r2), "=r"(r3) : "r"(addr));
}
__device__ __forceinline__ void hmma_f16(float* c, const uint32_t* a, const uint32_t* b) {
    asm volatile(
        "mma.sync.aligned.m16n8k16.row.col.f32.f16.f16.f32 "
        "{%0,%1,%2,%3}, {%4,%5,%6,%7}, {%8,%9}, {%0,%1,%2,%3};"
        : "+f"(c[0]), "+f"(c[1]), "+f"(c[2]), "+f"(c[3])
        : "r"(a[0]), "r"(a[1]), "r"(a[2]), "r"(a[3]), "r"(b[0]), "r"(b[1]));
}
__device__ __forceinline__ uint16_t f2h(float x) {
    __half h = __float2half_rn(x);
    return *(uint16_t*)&h;
}
__device__ __forceinline__ void hilo_h(float x, uint16_t& h, uint16_t& l) {
    __half hb = __float2half_rn(x);
    __half lb = __float2half_rn(x - __half2float(hb));
    h = *(uint16_t*)&hb;
    l = *(uint16_t*)&lb;
}
__device__ __forceinline__ uint32_t pk2(uint16_t a, uint16_t b) {
    return (uint32_t)a | ((uint32_t)b << 16);
}

struct LaneMap { int a_row, a_col, b_row, b_col; };

// ---------------------------------------------------------------------------
__global__ void clear_accum_kernel(int total) {
    int i = blockIdx.x * blockDim.x + threadIdx.x;
    if (i < total) g_tmp[i] = 0.0f;
}

// ---------------------------------------------------------------------------
// Kernel 1: t = relu(infeats @ W_rd + b_rd)
// ---------------------------------------------------------------------------
__global__ __launch_bounds__(TPB, 1)
void reduce_kernel(const float* __restrict__ infeats,
                   const float* __restrict__ W_rd,
                   const float* __restrict__ b_rd, int N) {
    __shared__ float Ws[SC * RED];
    __shared__ float rows[8 * SC];
    const int tid = threadIdx.x;
    const int base = blockIdx.x * 8;
    for (int i = tid; i < SC * RED; i += TPB) Ws[i] = W_rd[i];
    for (int i = tid; i < 8 * SC; i += TPB) {
        int nl = i >> 7, k = i & 127;
        rows[i] = (base + nl < N) ? infeats[(size_t)(base + nl) * SC + k] : 0.0f;
    }
    __syncthreads();
    const int nl = tid >> 5, r = tid & 31;
    float acc = b_rd[r];
#pragma unroll 8
    for (int i = 0; i < SC; i++) acc += rows[nl * SC + i] * Ws[i * RED + r];
    if (base + nl < N) g_t[(size_t)(base + nl) * RED + r] = fmaxf(acc, 0.0f);
}

// ---------------------------------------------------------------------------
// Kernel 2: fused edge MLP (mma.sync fp16 single-pass) + scatter-max.
// 512 threads / 16 warps; warp strip = 32 rows x 32 cols. (R11, unchanged.)
// ---------------------------------------------------------------------------
#define PLANE_B (128 * PX * 2)
#define OFF_X   0
#define OFF_W0  (OFF_X + PLANE_B)
#define OFF_W1  (OFF_W0 + PLANE_B)
#define OFF_CS  (OFF_W1 + PLANE_B)
#define OFF_NS  (OFF_CS + 512)
#define OFF_B0  (OFF_NS + 512)
#define OFF_B1  (OFF_B0 + 512)
#define EDGE_SMEM_BYTES (OFF_B1 + 512)

template <int KS>
__device__ __forceinline__ void gemm_strip(uint32_t x, uint32_t w,
                                           int wrow, int wcol, LaneMap lm,
                                           float acc[2][4][4]) {
#pragma unroll
    for (int m = 0; m < 2; m++)
#pragma unroll
        for (int n = 0; n < 4; n++)
#pragma unroll
            for (int i = 0; i < 4; i++) acc[m][n][i] = 0.f;

#pragma unroll 2
    for (int ks = 0; ks < KS; ks++) {
        const int k0 = ks * 16;
        uint32_t A[2][4];
#pragma unroll
        for (int m = 0; m < 2; m++) {
            uint32_t off = (uint32_t)((wrow + m * 16 + lm.a_row) * PX + k0 + lm.a_col) * 2;
            ldsm4(A[m][0], A[m][1], A[m][2], A[m][3], x + off);
        }
        uint32_t B[4][2];
#pragma unroll
        for (int nn = 0; nn < 2; nn++) {
            uint32_t off = (uint32_t)((wcol + nn * 16 + lm.b_row) * PX + k0 + lm.b_col) * 2;
            uint32_t r0, r1, r2, r3;
            ldsm4(r0, r1, r2, r3, w + off);
            B[nn * 2][0] = r0;     B[nn * 2][1] = r1;
            B[nn * 2 + 1][0] = r2; B[nn * 2 + 1][1] = r3;
        }
#pragma unroll
        for (int m = 0; m < 2; m++)
#pragma unroll
            for (int n = 0; n < 4; n++)
                hmma_f16(acc[m][n], A[m], B[n]);
    }
}

__global__ __launch_bounds__(ETPB, 1)
void edge_kernel(const float* __restrict__ pw,
                 const int* __restrict__ c_idx,
                 const int* __restrict__ n_idx,
                 const float* __restrict__ W0, const float* __restrict__ b0,
                 const float* __restrict__ W1, const float* __restrict__ b1,
                 int E, int ntiles) {
    extern __shared__ char smem[];
    const uint32_t sb = smem_addr32(smem);
    const uint32_t x  = sb + OFF_X;
    const uint32_t w0 = sb + OFF_W0;
    const uint32_t w1 = sb + OFF_W1;
    int*   cs  = (int*)(smem + OFF_CS);
    int*   ns  = (int*)(smem + OFF_NS);
    float* b0s = (float*)(smem + OFF_B0);
    float* b1s = (float*)(smem + OFF_B1);

    const int tid = threadIdx.x;
    const int wid = tid >> 5, lid = tid & 31;
    const int wrow = (wid & 3) * 32;
    const int wcol = (wid >> 2) * 32;
    const int g = lid >> 2, t = lid & 3;

    LaneMap lm;
    lm.a_row = (lid & 7) + ((lid >> 3) & 1) * 8;
    lm.a_col = ((lid >> 4) & 1) * 8;
    lm.b_row = (lid & 7) + ((lid >> 4) & 1) * 8;
    lm.b_col = ((lid >> 3) & 1) * 8;

    for (int idx = tid; idx < XDIM * PAIR; idx += ETPB) {
        int k = idx >> 7, j = idx & 127;
        *(uint16_t*)(smem + OFF_W0 + (uint32_t)(j * PX + k) * 2) = f2h(W0[idx]);
    }
    for (int idx = tid; idx < PAIR * PAIR; idx += ETPB) {
        int k = idx >> 7, j = idx & 127;
        *(uint16_t*)(smem + OFF_W1 + (uint32_t)(j * PX + k) * 2) = f2h(W1[idx]);
    }
    if (tid < PAIR) { b0s[tid] = b0[tid]; b1s[tid] = b1[tid]; }

    for (int tile = blockIdx.x; tile < ntiles; tile += gridDim.x) {
        const int base = tile * TS;
        const int nvalid = min(TS, E - base);
        __syncthreads();
        if (tid < TS) {
            bool ok = tid < nvalid;
            cs[tid] = ok ? c_idx[base + tid] : -1;
            ns[tid] = ok ? n_idx[base + tid] : -1;
        }
        __syncthreads();

        for (int idx = tid; idx < TS * 24; idx += ETPB) {
            int r = idx / 24, gg = idx - r * 24;
            float4 v = make_float4(0.f, 0.f, 0.f, 0.f);
            if (r < nvalid) {
                if (gg < 8) {
                    v = *(const float4*)&pw[(size_t)(base + r) * PWN + gg * 4];
                } else {
                    int c = cs[r], n = ns[r];
                    if (gg < 16) v = *(const float4*)&g_t[(size_t)c * RED + (gg - 8) * 4];
                    else if (n != c) v = *(const float4*)&g_t[(size_t)n * RED + (gg - 16) * 4];
                }
            }
            uint32_t o = (uint32_t)(r * PX + gg * 4) * 2;
            *(uint2*)(smem + OFF_X + o) =
                make_uint2(pk2(f2h(v.x), f2h(v.y)), pk2(f2h(v.z), f2h(v.w)));
        }
        __syncthreads();

        float acc[2][4][4];
        gemm_strip<6>(x, w0, wrow, wcol, lm, acc);
        __syncthreads();

#pragma unroll
        for (int m = 0; m < 2; m++) {
            const int r0 = wrow + m * 16 + g;
#pragma unroll
            for (int n = 0; n < 4; n++) {
                const int col = wcol + n * 8 + t * 2;
                const float bx = b0s[col], by = b0s[col + 1];
                float v0 = fmaxf(acc[m][n][0] + bx, 0.f);
                float v1 = fmaxf(acc[m][n][1] + by, 0.f);
                float v2 = fmaxf(acc[m][n][2] + bx, 0.f);
                float v3 = fmaxf(acc[m][n][3] + by, 0.f);
                uint32_t o0 = (uint32_t)(r0 * PX + col) * 2;
                uint32_t o1 = (uint32_t)((r0 + 8) * PX + col) * 2;
                *(uint32_t*)(smem + OFF_X + o0) = pk2(f2h(v0), f2h(v1));
                *(uint32_t*)(smem + OFF_X + o1) = pk2(f2h(v2), f2h(v3));
            }
        }
        __syncthreads();

        gemm_strip<8>(x, w1, wrow, wcol, lm, acc);

#pragma unroll
        for (int m = 0; m < 2; m++) {
            const int r0 = wrow + m * 16 + g;
            const int e0 = cs[r0], e1 = cs[r0 + 8];
#pragma unroll
            for (int n = 0; n < 4; n++) {
                const int col = wcol + n * 8 + t * 2;
                const float bx = b1s[col], by = b1s[col + 1];
                if (e0 >= 0) {
                    float v0 = acc[m][n][0] + bx;
                    float v1 = acc[m][n][1] + by;
                    float* dst = &g_tmp[(size_t)e0 * PAIR + col];
                    if (v0 > 0.f) atomicMax((int*)&dst[0], __float_as_int(v0));
                    if (v1 > 0.f) atomicMax((int*)&dst[1], __float_as_int(v1));
                }
                if (e1 >= 0) {
                    float v2 = acc[m][n][2] + bx;
                    float v3 = acc[m][n][3] + by;
                    float* dst = &g_tmp[(size_t)e1 * PAIR + col];
                    if (v2 > 0.f) atomicMax((int*)&dst[0], __float_as_int(v2));
                    if (v3 > 0.f) atomicMax((int*)&dst[1], __float_as_int(v3));
                }
            }
        }
    }
}

// ---------------------------------------------------------------------------
// Kernel 3: node MLP via mma.sync, fp16 hi/lo 3-pass (both operands).
// 64-node tiles, 256 threads / 8 warps; warp strip = 32 rows x 32 cols.
// ---------------------------------------------------------------------------
#define NTS 64
#define NOFF_AH 0
#define NOFF_AL (NOFF_AH + NTS * PX * 2)       // 17408
#define NOFF_WH (NOFF_AL + NTS * PX * 2)       // 34816
#define NOFF_WL (NOFF_WH + 128 * PX * 2)
#define NODE_SMEM_BYTES (NOFF_WL + 128 * PX * 2)   // 104448

// 3-pass strip over 8 k-steps: acc += Ah*Wh + Ah*Wl + Al*Wh
__device__ __forceinline__ void node_gemm(uint32_t ah, uint32_t al,
                                          uint32_t wh, uint32_t wl,
                                          int wrow, int wcol, LaneMap lm,
                                          float acc[2][4][4]) {
#pragma unroll
    for (int m = 0; m < 2; m++)
#pragma unroll
        for (int n = 0; n < 4; n++)
#pragma unroll
            for (int i = 0; i < 4; i++) acc[m][n][i] = 0.f;

#pragma unroll 2
    for (int ks = 0; ks < 8; ks++) {
        const int k0 = ks * 16;
        uint32_t Ah[2][4], Al[2][4];
#pragma unroll
        for (int m = 0; m < 2; m++) {
            uint32_t off = (uint32_t)((wrow + m * 16 + lm.a_row) * PX + k0 + lm.a_col) * 2;
            ldsm4(Ah[m][0], Ah[m][1], Ah[m][2], Ah[m][3], ah + off);
            ldsm4(Al[m][0], Al[m][1], Al[m][2], Al[m][3], al + off);
        }
        uint32_t Bh[4][2], Bl[4][2];
#pragma unroll
        for (int nn = 0; nn < 2; nn++) {
            uint32_t off = (uint32_t)((wcol + nn * 16 + lm.b_row) * PX + k0 + lm.b_col) * 2;
            uint32_t r0, r1, r2, r3;
            ldsm4(r0, r1, r2, r3, wh + off);
            Bh[nn * 2][0] = r0;     Bh[nn * 2][1] = r1;
            Bh[nn * 2 + 1][0] = r2; Bh[nn * 2 + 1][1] = r3;
            ldsm4(r0, r1, r2, r3, wl + off);
            Bl[nn * 2][0] = r0;     Bl[nn * 2][1] = r1;
            Bl[nn * 2 + 1][0] = r2; Bl[nn * 2 + 1][1] = r3;
        }
#pragma unroll
        for (int m = 0; m < 2; m++)
#pragma unroll
            for (int n = 0; n < 4; n++) {
                hmma_f16(acc[m][n], Ah[m], Bh[n]);
                hmma_f16(acc[m][n], Ah[m], Bl[n]);
                hmma_f16(acc[m][n], Al[m], Bh[n]);
            }
    }
}

__global__ __launch_bounds__(TPB, 1)
void node_kernel(const float* __restrict__ infeats,
                 const float* __restrict__ Wa, const float* __restrict__ ba,
                 const float* __restrict__ Wb, const float* __restrict__ bb_,
                 const float* __restrict__ W2, const float* __restrict__ b2,
                 float* __restrict__ out, int N) {
    extern __shared__ char smem[];
    const uint32_t sb = smem_addr32(smem);
    const uint32_t ah = sb + NOFF_AH, al = sb + NOFF_AL;
    const uint32_t wh = sb + NOFF_WH, wl = sb + NOFF_WL;

    const int tid = threadIdx.x;
    const int wid = tid >> 5, lid = tid & 31;
    const int base = blockIdx.x * NTS;
    const int nvalid = min(NTS, N - base);

    const int wrow = (wid & 1) * 32;         // 2 row strips x 4 col strips
    const int wcol = (wid >> 1) * 32;
    const int g = lid >> 2, t = lid & 3;

    LaneMap lm;
    lm.a_row = (lid & 7) + ((lid >> 3) & 1) * 8;
    lm.a_col = ((lid >> 4) & 1) * 8;
    lm.b_row = (lid & 7) + ((lid >> 4) & 1) * 8;
    lm.b_col = ((lid >> 3) & 1) * 8;

    // stage initial activations (g_tmp) hi/lo
    for (int idx = tid; idx < NTS * (PAIR / 4); idx += TPB) {
        int node = idx >> 5, k = (idx & 31) * 4;
        float4 v = make_float4(0.f, 0.f, 0.f, 0.f);
        if (node < nvalid) v = *(const float4*)&g_tmp[(size_t)(base + node) * PAIR + k];
        uint16_t h0,l0,h1,l1,h2,l2,h3,l3;
        hilo_h(v.x,h0,l0); hilo_h(v.y,h1,l1); hilo_h(v.z,h2,l2); hilo_h(v.w,h3,l3);
        uint32_t o = (uint32_t)(node * PX + k) * 2;
        *(uint2*)(smem + NOFF_AH + o) = make_uint2(pk2(h0,h1), pk2(h2,h3));
        *(uint2*)(smem + NOFF_AL + o) = make_uint2(pk2(l0,l1), pk2(l2,l3));
    }

    const float* Wp[3] = {Wa, Wb, W2};
    const float* bp[3] = {ba, bb_, b2};

    for (int layer = 0; layer < 3; layer++) {
        __syncthreads();   // prev epilogue acts writes done; all warps past prev MMA
        // stage W[layer]: transpose W[k][j] -> planes[j][k], hi/lo
        const float* Wsrc = Wp[layer];
        for (int idx = tid; idx < PAIR * PAIR; idx += TPB) {
            int k = idx >> 7, j = idx & 127;
            uint16_t h, l; hilo_h(Wsrc[idx], h, l);
            uint32_t o = (uint32_t)(j * PX + k) * 2;
            *(uint16_t*)(smem + NOFF_WH + o) = h;
            *(uint16_t*)(smem + NOFF_WL + o) = l;
        }
        __syncthreads();   // weights ready

        float acc[2][4][4];
        node_gemm(ah, al, wh, wl, wrow, wcol, lm, acc);
        __syncthreads();   // all acts/W reads done before epilogue overwrites acts

        if (layer < 2) {
#pragma unroll
            for (int m = 0; m < 2; m++) {
                const int r0 = wrow + m * 16 + g;
#pragma unroll
                for (int n = 0; n < 4; n++) {
                    const int col = wcol + n * 8 + t * 2;
                    const float bx = bp[layer][col], by = bp[layer][col + 1];
                    float v0 = fmaxf(acc[m][n][0] + bx, 0.f);
                    float v1 = fmaxf(acc[m][n][1] + by, 0.f);
                    float v2 = fmaxf(acc[m][n][2] + bx, 0.f);
                    float v3 = fmaxf(acc[m][n][3] + by, 0.f);
                    uint16_t h0,l0,h1,l1,h2,l2,h3,l3;
                    hilo_h(v0,h0,l0); hilo_h(v1,h1,l1);
                    hilo_h(v2,h2,l2); hilo_h(v3,h3,l3);
                    uint32_t o0 = (uint32_t)(r0 * PX + col) * 2;
                    uint32_t o1 = (uint32_t)((r0 + 8) * PX + col) * 2;
                    *(uint32_t*)(smem + NOFF_AH + o0) = pk2(h0, h1);
                    *(uint32_t*)(smem + NOFF_AL + o0) = pk2(l0, l1);
                    *(uint32_t*)(smem + NOFF_AH + o1) = pk2(h2, h3);
                    *(uint32_t*)(smem + NOFF_AL + o1) = pk2(l2, l3);
                }
            }
        } else {
            // final: out = relu(acc + bias + infeats)
#pragma unroll
            for (int m = 0; m < 2; m++) {
#pragma unroll
                for (int rr = 0; rr < 2; rr++) {
                    const int node = wrow + m * 16 + g + rr * 8;
                    if (node < nvalid) {
                        const float* inrow = &infeats[(size_t)(base + node) * SC];
                        float* orow = &out[(size_t)(base + node) * SC];
#pragma unroll
                        for (int n = 0; n < 4; n++) {
                            const int col = wcol + n * 8 + t * 2;
                            const float bx = bp[2][col], by = bp[2][col + 1];
                            float a0 = acc[m][n][rr * 2 + 0];
                            float a1 = acc[m][n][rr * 2 + 1];
                            orow[col]     = fmaxf(a0 + bx + inrow[col], 0.f);
                            orow[col + 1] = fmaxf(a1 + by + inrow[col + 1], 0.f);
                        }
                    }
                }
            }
        }
    }
}

// ---------------------------------------------------------------------------
extern "C" void kernel_launch(void* const* d_in, const int* in_sizes, int n_in,
                              void* d_out, int out_size) {
    const float* infeats = (const float*)d_in[0];
    const float* pw      = (const float*)d_in[1];
    const int*   c_idxs  = (const int*)d_in[2];
    const int*   n_idxs  = (const int*)d_in[3];
    const float* W_rd  = (const float*)d_in[5];
    const float* b_rd  = (const float*)d_in[6];
    const float* W_pw0 = (const float*)d_in[7];
    const float* b_pw0 = (const float*)d_in[8];
    const float* W_pw1 = (const float*)d_in[9];
    const float* b_pw1 = (const float*)d_in[10];
    const float* W_f1a = (const float*)d_in[11];
    const float* b_f1a = (const float*)d_in[12];
    const float* W_f1b = (const float*)d_in[13];
    const float* b_f1b = (const float*)d_in[14];
    const float* W_f2  = (const float*)d_in[15];
    const float* b_f2  = (const float*)d_in[16];
    float* out = (float*)d_out;

    const int N = in_sizes[0] / SC;
    const int E = in_sizes[1] / PWN;

    cudaFuncSetAttribute(edge_kernel, cudaFuncAttributeMaxDynamicSharedMemorySize,
                         EDGE_SMEM_BYTES);
    cudaFuncSetAttribute(node_kernel, cudaFuncAttributeMaxDynamicSharedMemorySize,
                         NODE_SMEM_BYTES);

    const int tot = N * PAIR;
    clear_accum_kernel<<<(tot + 255) / 256, 256>>>(tot);

    reduce_kernel<<<(N + 7) / 8, TPB>>>(infeats, W_rd, b_rd, N);

    const int ntiles = (E + TS - 1) / TS;
    const int grid = ntiles < 148 ? ntiles : 148;
    edge_kernel<<<grid, ETPB, EDGE_SMEM_BYTES>>>(pw, c_idxs, n_idxs,
                                                 W_pw0, b_pw0, W_pw1, b_pw1,
                                                 E, ntiles);

    node_kernel<<<(N + NTS - 1) / NTS, TPB, NODE_SMEM_BYTES>>>(
        infeats, W_f1a, b_f1a, W_f1b, b_f1b, W_f2, b_f2, out, N);
}

// round 15
// speedup vs baseline: 1.0577x; 1.0577x over previous
#include <cuda_runtime.h>
#include <cuda_fp16.h>
#include <cstdint>

// v14 (= v13 re-spin): edge fp16 single-pass, TS=256 tiles, fp16 node feats;
// node fp32 (R8 form).
#define N_MAX 16384
#define SC    128
#define RED   32
#define PWN   32
#define PAIR  128
#define XDIM  96

#define TPB  256
#define ETPB 512
#define TS2  256
#define PX   136     // fp16 element pitch of activation/weight planes

__device__ __half g_t_h[(size_t)N_MAX * RED];   // reduced node feats (fp16)
__device__ float  g_tmp[(size_t)N_MAX * PAIR];  // scatter-max accumulator

// ---------------------------------------------------------------------------
// helpers
// ---------------------------------------------------------------------------
__device__ __forceinline__ uint32_t sm32(const void* p) {
    uint32_t a;
    asm("{ .reg .u64 t; cvta.to.shared.u64 t, %1; cvt.u32.u64 %0, t; }" : "=r"(a) : "l"(p));
    return a;
}
__device__ __forceinline__ void ldmx4(uint32_t& r0, uint32_t& r1, uint32_t& r2,
                                      uint32_t& r3, uint32_t addr) {
    asm volatile("ldmatrix.sync.aligned.m8n8.x4.shared.b16 {%0,%1,%2,%3}, [%4];"
                 : "=r"(r0), "=r"(r1), "=r"(r2), "=r"(r3) : "r"(addr));
}
__device__ __forceinline__ void mma16(float* c, const uint32_t* a, const uint32_t* b) {
    asm volatile(
        "mma.sync.aligned.m16n8k16.row.col.f32.f16.f16.f32 "
        "{%0,%1,%2,%3}, {%4,%5,%6,%7}, {%8,%9}, {%0,%1,%2,%3};"
        : "+f"(c[0]), "+f"(c[1]), "+f"(c[2]), "+f"(c[3])
        : "r"(a[0]), "r"(a[1]), "r"(a[2]), "r"(a[3]), "r"(b[0]), "r"(b[1]));
}
__device__ __forceinline__ uint16_t f2h(float x) {
    __half h = __float2half_rn(x);
    return *(uint16_t*)&h;
}
__device__ __forceinline__ uint32_t pk2(uint16_t a, uint16_t b) {
    return (uint32_t)a | ((uint32_t)b << 16);
}

struct LaneMap { int a_row, a_col, b_row, b_col; };

// ---------------------------------------------------------------------------
__global__ void clear_accum_kernel(int total) {
    int i = blockIdx.x * blockDim.x + threadIdx.x;
    if (i < total) g_tmp[i] = 0.0f;
}

// ---------------------------------------------------------------------------
// Kernel 1: t = relu(infeats @ W_rd + b_rd), stored directly as fp16
// ---------------------------------------------------------------------------
__global__ __launch_bounds__(TPB, 1)
void reduce_kernel(const float* __restrict__ infeats,
                   const float* __restrict__ W_rd,
                   const float* __restrict__ b_rd, int N) {
    __shared__ float Ws[SC * RED];
    __shared__ float rows[8 * SC];
    const int tid = threadIdx.x;
    const int base = blockIdx.x * 8;
    for (int i = tid; i < SC * RED; i += TPB) Ws[i] = W_rd[i];
    for (int i = tid; i < 8 * SC; i += TPB) {
        int nl = i >> 7, k = i & 127;
        rows[i] = (base + nl < N) ? infeats[(size_t)(base + nl) * SC + k] : 0.0f;
    }
    __syncthreads();
    const int nl = tid >> 5, r = tid & 31;
    float acc = b_rd[r];
#pragma unroll 8
    for (int i = 0; i < SC; i++) acc += rows[nl * SC + i] * Ws[i * RED + r];
    if (base + nl < N)
        g_t_h[(size_t)(base + nl) * RED + r] = __float2half_rn(fmaxf(acc, 0.0f));
}

// ---------------------------------------------------------------------------
// Kernel 2: fused edge MLP (mma.sync fp16 single-pass) + scatter-max.
// 512 threads / 16 warps; tile = 256 edges; warp strip = 32 rows x 64 cols.
// ---------------------------------------------------------------------------
#define XPLANE_B (TS2 * PX * 2)     // 69632
#define WPLANE_B (128 * PX * 2)     // 34816
#define OFF_X   0
#define OFF_W0  (OFF_X + XPLANE_B)
#define OFF_W1  (OFF_W0 + WPLANE_B)
#define OFF_CS  (OFF_W1 + WPLANE_B)
#define OFF_NS  (OFF_CS + 1024)
#define OFF_B0  (OFF_NS + 1024)
#define OFF_B1  (OFF_B0 + 512)
#define EDGE_SMEM_BYTES (OFF_B1 + 512)

// warp strip GEMM: 32 rows (2 m16) x 64 cols (8 n8); B consumed immediately
template <int KS>
__device__ __forceinline__ void gemm_strip(uint32_t x, uint32_t w,
                                           int wrow, int wcol, LaneMap lm,
                                           float acc[2][8][4]) {
#pragma unroll
    for (int m = 0; m < 2; m++)
#pragma unroll
        for (int n = 0; n < 8; n++)
#pragma unroll
            for (int i = 0; i < 4; i++) acc[m][n][i] = 0.f;

#pragma unroll 2
    for (int ks = 0; ks < KS; ks++) {
        const int k0 = ks * 16;
        uint32_t A[2][4];
#pragma unroll
        for (int m = 0; m < 2; m++) {
            uint32_t off = (uint32_t)((wrow + m * 16 + lm.a_row) * PX + k0 + lm.a_col) * 2;
            ldmx4(A[m][0], A[m][1], A[m][2], A[m][3], x + off);
        }
#pragma unroll
        for (int nn = 0; nn < 4; nn++) {
            uint32_t off = (uint32_t)((wcol + nn * 16 + lm.b_row) * PX + k0 + lm.b_col) * 2;
            uint32_t b0, b1, b2, b3;
            ldmx4(b0, b1, b2, b3, w + off);
            uint32_t Ba[2] = {b0, b1}, Bb[2] = {b2, b3};
#pragma unroll
            for (int m = 0; m < 2; m++) {
                mma16(acc[m][nn * 2],     A[m], Ba);
                mma16(acc[m][nn * 2 + 1], A[m], Bb);
            }
        }
    }
}

__global__ __launch_bounds__(ETPB, 1)
void edge_kernel(const float* __restrict__ pw,
                 const int* __restrict__ c_idx,
                 const int* __restrict__ n_idx,
                 const float* __restrict__ W0, const float* __restrict__ b0,
                 const float* __restrict__ W1, const float* __restrict__ b1,
                 int E, int ntiles) {
    extern __shared__ char smem[];
    const uint32_t sb = sm32(smem);
    const uint32_t x  = sb + OFF_X;
    const uint32_t w0 = sb + OFF_W0;
    const uint32_t w1 = sb + OFF_W1;
    int*   cs  = (int*)(smem + OFF_CS);
    int*   ns  = (int*)(smem + OFF_NS);
    float* b0s = (float*)(smem + OFF_B0);
    float* b1s = (float*)(smem + OFF_B1);

    const int tid = threadIdx.x;
    const int wid = tid >> 5, lid = tid & 31;
    const int wrow = (wid & 7) * 32;     // 8 row strips x 2 col strips
    const int wcol = (wid >> 3) * 64;
    const int g = lid >> 2, t = lid & 3;

    LaneMap lm;
    lm.a_row = (lid & 7) + ((lid >> 3) & 1) * 8;
    lm.a_col = ((lid >> 4) & 1) * 8;
    lm.b_row = (lid & 7) + ((lid >> 4) & 1) * 8;
    lm.b_col = ((lid >> 3) & 1) * 8;

    // weights: transpose W[k][j] -> plane[j][k], fp16
    for (int idx = tid; idx < XDIM * PAIR; idx += ETPB) {
        int k = idx >> 7, j = idx & 127;
        *(uint16_t*)(smem + OFF_W0 + (uint32_t)(j * PX + k) * 2) = f2h(W0[idx]);
    }
    for (int idx = tid; idx < PAIR * PAIR; idx += ETPB) {
        int k = idx >> 7, j = idx & 127;
        *(uint16_t*)(smem + OFF_W1 + (uint32_t)(j * PX + k) * 2) = f2h(W1[idx]);
    }
    if (tid < PAIR) { b0s[tid] = b0[tid]; b1s[tid] = b1[tid]; }

    for (int tile = blockIdx.x; tile < ntiles; tile += gridDim.x) {
        const int base = tile * TS2;
        const int nvalid = min(TS2, E - base);
        __syncthreads();   // previous tile fully consumed
        if (tid < TS2) {
            bool ok = tid < nvalid;
            cs[tid] = ok ? c_idx[base + tid] : -1;
            ns[tid] = ok ? n_idx[base + tid] : -1;
        }
        __syncthreads();

        // gather X rows (edges): pw (8 quad groups) + c/n feats (fp16 uint4)
        for (int idx = tid; idx < TS2 * 16; idx += ETPB) {
            int r = idx >> 4, gg = idx & 15;
            if (gg < 8) {
                float4 v = make_float4(0.f, 0.f, 0.f, 0.f);
                if (r < nvalid)
                    v = *(const float4*)&pw[(size_t)(base + r) * PWN + gg * 4];
                uint32_t o = (uint32_t)(r * PX + gg * 4) * 2;
                *(uint2*)(smem + OFF_X + o) =
                    make_uint2(pk2(f2h(v.x), f2h(v.y)), pk2(f2h(v.z), f2h(v.w)));
            } else {
                int hi = gg - 8;   // 0..3 c-feats, 4..7 n-feats (8 halves each)
                uint4 v = make_uint4(0u, 0u, 0u, 0u);
                if (r < nvalid) {
                    int c = cs[r];
                    if (hi < 4) {
                        v = *(const uint4*)&g_t_h[(size_t)c * RED + hi * 8];
                    } else {
                        int n = ns[r];
                        if (n != c)
                            v = *(const uint4*)&g_t_h[(size_t)n * RED + (hi - 4) * 8];
                    }
                }
                uint32_t col = 32 + hi * 8;
                *(uint4*)(smem + OFF_X + (uint32_t)(r * PX + col) * 2) = v;
            }
        }
        __syncthreads();

        // GEMM1: K = 96
        float acc[2][8][4];
        gemm_strip<6>(x, w0, wrow, wcol, lm, acc);
        __syncthreads();   // X reads complete before H1 overwrite

        // epilogue 1: relu(acc+b0) -> fp16 -> H1 plane (in place of X)
#pragma unroll
        for (int m = 0; m < 2; m++) {
            const int r0 = wrow + m * 16 + g;
#pragma unroll
            for (int n = 0; n < 8; n++) {
                const int col = wcol + n * 8 + t * 2;
                const float bx = b0s[col], by = b0s[col + 1];
                float v0 = fmaxf(acc[m][n][0] + bx, 0.f);
                float v1 = fmaxf(acc[m][n][1] + by, 0.f);
                float v2 = fmaxf(acc[m][n][2] + bx, 0.f);
                float v3 = fmaxf(acc[m][n][3] + by, 0.f);
                uint32_t o0 = (uint32_t)(r0 * PX + col) * 2;
                uint32_t o1 = (uint32_t)((r0 + 8) * PX + col) * 2;
                *(uint32_t*)(smem + OFF_X + o0) = pk2(f2h(v0), f2h(v1));
                *(uint32_t*)(smem + OFF_X + o1) = pk2(f2h(v2), f2h(v3));
            }
        }
        __syncthreads();

        // GEMM2: K = 128
        gemm_strip<8>(x, w1, wrow, wcol, lm, acc);

        // epilogue 2: relu(acc+b1) -> scatter atomicMax (values >= 0)
#pragma unroll
        for (int m = 0; m < 2; m++) {
            const int r0 = wrow + m * 16 + g;
            const int e0 = cs[r0], e1 = cs[r0 + 8];
#pragma unroll
            for (int n = 0; n < 8; n++) {
                const int col = wcol + n * 8 + t * 2;
                const float bx = b1s[col], by = b1s[col + 1];
                if (e0 >= 0) {
                    float v0 = acc[m][n][0] + bx;
                    float v1 = acc[m][n][1] + by;
                    float* dst = &g_tmp[(size_t)e0 * PAIR + col];
                    if (v0 > 0.f) atomicMax((int*)&dst[0], __float_as_int(v0));
                    if (v1 > 0.f) atomicMax((int*)&dst[1], __float_as_int(v1));
                }
                if (e1 >= 0) {
                    float v2 = acc[m][n][2] + bx;
                    float v3 = acc[m][n][3] + by;
                    float* dst = &g_tmp[(size_t)e1 * PAIR + col];
                    if (v2 > 0.f) atomicMax((int*)&dst[0], __float_as_int(v2));
                    if (v3 > 0.f) atomicMax((int*)&dst[1], __float_as_int(v3));
                }
            }
        }
    }
}

// ---------------------------------------------------------------------------
// Kernel 3: node MLP, 64-node tiles, 256 threads, per-layer weight staging.
// ---------------------------------------------------------------------------
#define NTS 64
#define ACT_LD 132
#define NODE_SMEM_BYTES ((NTS*ACT_LD + PAIR*PAIR) * 4)

__global__ __launch_bounds__(TPB, 1)
void node_kernel(const float* __restrict__ infeats,
                 const float* __restrict__ Wa, const float* __restrict__ ba,
                 const float* __restrict__ Wb, const float* __restrict__ bb_,
                 const float* __restrict__ W2, const float* __restrict__ b2,
                 float* __restrict__ out, int N) {
    extern __shared__ float smemf[];
    float* acts = smemf;                 // 64 x 132
    float* Ws   = smemf + NTS * ACT_LD;  // 128 x 128

    const int tid = threadIdx.x;
    const int base = blockIdx.x * NTS;
    const int nvalid = min(NTS, N - base);

    for (int idx = tid; idx < NTS * (PAIR / 4); idx += TPB) {
        int node = idx >> 5, k = (idx & 31) * 4;
        float4 v = make_float4(0.f, 0.f, 0.f, 0.f);
        if (node < nvalid) v = *(const float4*)&g_tmp[(size_t)(base + node) * PAIR + k];
        *(float4*)&acts[node * ACT_LD + k] = v;
    }

    const int tx = tid & 15, ty = tid >> 4;
    const int col0 = tx * 8, row0 = ty * 4;

    const float* Wp[3] = {Wa, Wb, W2};
    const float* bp[3] = {ba, bb_, b2};

    for (int layer = 0; layer < 3; layer++) {
        __syncthreads();
        for (int i = tid * 4; i < PAIR * PAIR; i += TPB * 4)
            *(float4*)&Ws[i] = *(const float4*)&Wp[layer][i];
        __syncthreads();

        float acc[4][8];
#pragma unroll
        for (int r = 0; r < 4; r++)
#pragma unroll
            for (int c = 0; c < 8; c++) acc[r][c] = 0.f;

        for (int k = 0; k < PAIR; k += 4) {
            float4 a[4];
#pragma unroll
            for (int r = 0; r < 4; r++)
                a[r] = *(float4*)&acts[(row0 + r) * ACT_LD + k];
#pragma unroll
            for (int kk = 0; kk < 4; kk++) {
                float4 w0 = *(float4*)&Ws[(k + kk) * PAIR + col0];
                float4 w1 = *(float4*)&Ws[(k + kk) * PAIR + col0 + 4];
                float b[8] = {w0.x, w0.y, w0.z, w0.w, w1.x, w1.y, w1.z, w1.w};
#pragma unroll
                for (int r = 0; r < 4; r++) {
                    float av = (kk == 0) ? a[r].x : (kk == 1) ? a[r].y
                             : (kk == 2) ? a[r].z : a[r].w;
#pragma unroll
                    for (int c = 0; c < 8; c++) acc[r][c] += av * b[c];
                }
            }
        }
        __syncthreads();

        float bias[8];
#pragma unroll
        for (int c = 0; c < 8; c++) bias[c] = bp[layer][col0 + c];

        if (layer < 2) {
#pragma unroll
            for (int r = 0; r < 4; r++) {
                float4 v0, v1;
                v0.x = fmaxf(acc[r][0] + bias[0], 0.f);
                v0.y = fmaxf(acc[r][1] + bias[1], 0.f);
                v0.z = fmaxf(acc[r][2] + bias[2], 0.f);
                v0.w = fmaxf(acc[r][3] + bias[3], 0.f);
                v1.x = fmaxf(acc[r][4] + bias[4], 0.f);
                v1.y = fmaxf(acc[r][5] + bias[5], 0.f);
                v1.z = fmaxf(acc[r][6] + bias[6], 0.f);
                v1.w = fmaxf(acc[r][7] + bias[7], 0.f);
                *(float4*)&acts[(row0 + r) * ACT_LD + col0]     = v0;
                *(float4*)&acts[(row0 + r) * ACT_LD + col0 + 4] = v1;
            }
        } else {
#pragma unroll
            for (int r = 0; r < 4; r++) {
                int node = row0 + r;
                if (node < nvalid) {
                    const float* inrow = &infeats[(size_t)(base + node) * SC + col0];
                    float* orow = &out[(size_t)(base + node) * SC + col0];
                    float4 i0 = *(const float4*)&inrow[0];
                    float4 i1 = *(const float4*)&inrow[4];
                    float4 v0, v1;
                    v0.x = fmaxf(acc[r][0] + bias[0] + i0.x, 0.f);
                    v0.y = fmaxf(acc[r][1] + bias[1] + i0.y, 0.f);
                    v0.z = fmaxf(acc[r][2] + bias[2] + i0.z, 0.f);
                    v0.w = fmaxf(acc[r][3] + bias[3] + i0.w, 0.f);
                    v1.x = fmaxf(acc[r][4] + bias[4] + i1.x, 0.f);
                    v1.y = fmaxf(acc[r][5] + bias[5] + i1.y, 0.f);
                    v1.z = fmaxf(acc[r][6] + bias[6] + i1.z, 0.f);
                    v1.w = fmaxf(acc[r][7] + bias[7] + i1.w, 0.f);
                    *(float4*)&orow[0] = v0;
                    *(float4*)&orow[4] = v1;
                }
            }
        }
    }
}

// ---------------------------------------------------------------------------
extern "C" void kernel_launch(void* const* d_in, const int* in_sizes, int n_in,
                              void* d_out, int out_size) {
    const float* infeats = (const float*)d_in[0];
    const float* pw      = (const float*)d_in[1];
    const int*   c_idxs  = (const int*)d_in[2];
    const int*   n_idxs  = (const int*)d_in[3];
    const float* W_rd  = (const float*)d_in[5];
    const float* b_rd  = (const float*)d_in[6];
    const float* W_pw0 = (const float*)d_in[7];
    const float* b_pw0 = (const float*)d_in[8];
    const float* W_pw1 = (const float*)d_in[9];
    const float* b_pw1 = (const float*)d_in[10];
    const float* W_f1a = (const float*)d_in[11];
    const float* b_f1a = (const float*)d_in[12];
    const float* W_f1b = (const float*)d_in[13];
    const float* b_f1b = (const float*)d_in[14];
    const float* W_f2  = (const float*)d_in[15];
    const float* b_f2  = (const float*)d_in[16];
    float* out = (float*)d_out;

    const int N = in_sizes[0] / SC;
    const int E = in_sizes[1] / PWN;

    cudaFuncSetAttribute(edge_kernel, cudaFuncAttributeMaxDynamicSharedMemorySize,
                         EDGE_SMEM_BYTES);
    cudaFuncSetAttribute(node_kernel, cudaFuncAttributeMaxDynamicSharedMemorySize,
                         NODE_SMEM_BYTES);

    const int tot = N * PAIR;
    clear_accum_kernel<<<(tot + 255) / 256, 256>>>(tot);

    reduce_kernel<<<(N + 7) / 8, TPB>>>(infeats, W_rd, b_rd, N);

    const int ntiles = (E + TS2 - 1) / TS2;
    const int grid = ntiles < 148 ? ntiles : 148;
    edge_kernel<<<grid, ETPB, EDGE_SMEM_BYTES>>>(pw, c_idxs, n_idxs,
                                                 W_pw0, b_pw0, W_pw1, b_pw1,
                                                 E, ntiles);

    node_kernel<<<(N + NTS - 1) / NTS, TPB, NODE_SMEM_BYTES>>>(
        infeats, W_f1a, b_f1a, W_f1b, b_f1b, W_f2, b_f2, out, N);
}